// round 6
// baseline (speedup 1.0000x reference)
#include <cuda_runtime.h>
#include <cuda_bf16.h>
#include <cstdint>

#define C      128
#define NTOT   16384
#define BATCH  16
#define WSB    272      // weight smem row stride bytes (128 bf16 + 8 pad)
#define XSB    528      // x/V/q smem row stride bytes (256 bf16 + 8 pad)
#define WBUF   34816    // 128 * WSB
#define XBUF   67584    // 128 * XSB
#define TPX    256      // pixels per tile
#define NTILE  64       // tiles per batch
#define BPB    9        // blocks per batch

__device__ float g_S[BATCH][8][16][16];
__device__ float g_Z[BATCH][C];
__device__ float g_G[BATCH][C][C];

// ---------------- primitives ----------------
__device__ __forceinline__ void mma_bf16(float d[4], const uint32_t a[4], uint32_t b0, uint32_t b1) {
    asm volatile(
        "mma.sync.aligned.m16n8k16.row.col.f32.bf16.bf16.f32 "
        "{%0,%1,%2,%3}, {%4,%5,%6,%7}, {%8,%9}, {%0,%1,%2,%3};"
        : "+f"(d[0]), "+f"(d[1]), "+f"(d[2]), "+f"(d[3])
        : "r"(a[0]), "r"(a[1]), "r"(a[2]), "r"(a[3]), "r"(b0), "r"(b1));
}
__device__ __forceinline__ void ldsm4(uint32_t r[4], uint32_t addr) {
    asm volatile("ldmatrix.sync.aligned.m8n8.x4.shared.b16 {%0,%1,%2,%3}, [%4];"
                 : "=r"(r[0]), "=r"(r[1]), "=r"(r[2]), "=r"(r[3]) : "r"(addr));
}
__device__ __forceinline__ void ldsm4t(uint32_t r[4], uint32_t addr) {
    asm volatile("ldmatrix.sync.aligned.m8n8.x4.trans.shared.b16 {%0,%1,%2,%3}, [%4];"
                 : "=r"(r[0]), "=r"(r[1]), "=r"(r[2]), "=r"(r[3]) : "r"(addr));
}
__device__ __forceinline__ uint32_t packbf(float lo, float hi) {
    __nv_bfloat162 h = __floats2bfloat162_rn(lo, hi);
    return *(uint32_t*)&h;
}
__device__ __forceinline__ float fexp(float x) {   // FMA-pipe exp
    float y = x * 1.4426950408889634f;
    float r = rintf(y);
    float f = y - r;
    float p = 0.0096181291f;
    p = fmaf(p, f, 0.0555041086f);
    p = fmaf(p, f, 0.2402265069f);
    p = fmaf(p, f, 0.6931471806f);
    p = fmaf(p, f, 1.0f);
    return __int_as_float(__float_as_int(p) + ((int)r << 23));
}

// 32x64 warp tile of a 128(row)x256(px)x128(k) GEMM, 16 warps (4 row-bands x 4 col-bands).
// A: [m][k] bf16, stride WSB, non-trans ldmatrix. B: [k][n] bf16, stride XSB, trans ldmatrix.
// acc[2 mtiles][8 ntiles][4].
__device__ __forceinline__ void gemm_warpT(uint32_t aA, uint32_t aB, float acc[2][8][4],
                                           int lane, int rm, int cn) {
    const int m = lane >> 3, lr = lane & 7;
    const uint32_t aA0 = aA + (uint32_t)(rm + (m & 1) * 8 + lr) * WSB + (m >> 1) * 16;
    const uint32_t aB0 = aB + (uint32_t)((m & 1) * 8 + lr) * XSB + (cn + (m >> 1) * 8) * 2;
#pragma unroll
    for (int kb = 0; kb < 8; kb++) {
        uint32_t a[2][4];
        ldsm4(a[0], aA0 + kb * 32);
        ldsm4(a[1], aA0 + 16 * WSB + kb * 32);
#pragma unroll
        for (int p = 0; p < 4; p++) {
            uint32_t b[4];
            ldsm4t(b, aB0 + (uint32_t)kb * 16 * XSB + p * 32);
            mma_bf16(acc[0][2 * p],     a[0], b[0], b[1]);
            mma_bf16(acc[0][2 * p + 1], a[0], b[2], b[3]);
            mma_bf16(acc[1][2 * p],     a[1], b[0], b[1]);
            mma_bf16(acc[1][2 * p + 1], a[1], b[2], b[3]);
        }
    }
}

// x tile: gmem [c][n] f32 -> smem [c][n] bf16 (stride XSB). Coalesced LDG, conflict-free STS.128.
__device__ __forceinline__ void load_x(char* s, const float* __restrict__ xg, int t) {
    const int c0 = t >> 3;          // 0..63
    const int nl = (t & 7) * 8;     // 0..56
#pragma unroll
    for (int h = 0; h < 2; h++) {
        const int cc = c0 + h * 64;
        const float* src = xg + (size_t)cc * NTOT;
        char* dst = s + cc * XSB;
#pragma unroll
        for (int j = 0; j < 4; j++) {
            int n0 = nl + j * 64;
            float4 v0 = *(const float4*)(src + n0);
            float4 v1 = *(const float4*)(src + n0 + 4);
            uint4 p;
            p.x = packbf(v0.x, v0.y);
            p.y = packbf(v0.z, v0.w);
            p.z = packbf(v1.x, v1.y);
            p.w = packbf(v1.z, v1.w);
            *(uint4*)(dst + n0 * 2) = p;
        }
    }
}
// 128x128 f32 row-major -> bf16 smem (stride WSB), 512 threads
__device__ __forceinline__ void load_w(char* s, const float* __restrict__ W, int t) {
#pragma unroll
    for (int i = 0; i < 8; i++) {
        int idx = i * 512 + t;
        int mm = idx >> 5, k4 = (idx & 31) * 4;
        float4 v = *(const float4*)(W + mm * C + k4);
        *(uint2*)(s + mm * WSB + k4 * 2) = make_uint2(packbf(v.x, v.y), packbf(v.z, v.w));
    }
}

__global__ void zero_kernel() {
    int t = blockIdx.x * blockDim.x + threadIdx.x;
    if (t < BATCH * 8 * 16 * 16) (&g_S[0][0][0][0])[t] = 0.f;
    if (t < BATCH * C) (&g_Z[0][0])[t] = 0.f;
}

// ================= Pass A =================
__global__ void __launch_bounds__(512, 1)
passA_kernel(const float* __restrict__ x, const float* __restrict__ Wk,
             const float* __restrict__ bk, const float* __restrict__ Wv,
             const float* __restrict__ bv) {
    extern __shared__ char sm[];
    char* sWk = sm;
    char* sWv = sm + WBUF;
    char* sV  = sm + 2 * WBUF;
    char* sX  = sm + 2 * WBUF + XBUF;
    const uint32_t aWk = (uint32_t)__cvta_generic_to_shared(sWk);
    const uint32_t aWv = (uint32_t)__cvta_generic_to_shared(sWv);
    const uint32_t aV  = (uint32_t)__cvta_generic_to_shared(sV);
    const uint32_t aX  = (uint32_t)__cvta_generic_to_shared(sX);

    const int t = threadIdx.x, l = t & 31, w = t >> 5;
    const int g = l >> 2, tig = l & 3, m = l >> 3, lr = l & 7;
    const int rm = (w & 3) * 32, cn = (w >> 2) * 64;
    const int b = blockIdx.y;
    const float* xb = x + (size_t)b * C * NTOT;

    load_w(sWk, Wk, t);
    load_w(sWv, Wv, t);

    float bk0[2], bk1[2], bv0[2], bv1[2];
#pragma unroll
    for (int mt = 0; mt < 2; mt++) {
        bk0[mt] = bk[rm + mt * 16 + g];     bk1[mt] = bk[rm + mt * 16 + 8 + g];
        bv0[mt] = bv[rm + mt * 16 + g];     bv1[mt] = bv[rm + mt * 16 + 8 + g];
    }

    float accS[2][2][4];
    float zacc[2][2] = {{0.f, 0.f}, {0.f, 0.f}};
#pragma unroll
    for (int mt = 0; mt < 2; mt++)
#pragma unroll
        for (int p = 0; p < 2; p++)
#pragma unroll
            for (int j = 0; j < 4; j++) accS[mt][p][j] = 0.f;

    const int h0 = rm >> 4;
    for (int tt = blockIdx.x; tt < NTILE; tt += BPB) {
        load_x(sX, xb + tt * TPX, t);
        __syncthreads();

        float acc[2][8][4];
        // values GEMM
#pragma unroll
        for (int mt = 0; mt < 2; mt++)
#pragma unroll
            for (int nt = 0; nt < 8; nt++)
#pragma unroll
                for (int j = 0; j < 4; j++) acc[mt][nt][j] = 0.f;
        gemm_warpT(aWv, aX, acc, l, rm, cn);

        // scatter V+bv -> sV [v][n] (conflict-free u32)
#pragma unroll
        for (int mt = 0; mt < 2; mt++) {
            const int r0 = rm + mt * 16 + g;
#pragma unroll
            for (int nt = 0; nt < 8; nt++) {
                const int n0 = cn + nt * 8 + tig * 2;
                *(uint32_t*)(sV + r0 * XSB + n0 * 2)       = packbf(acc[mt][nt][0] + bv0[mt], acc[mt][nt][1] + bv0[mt]);
                *(uint32_t*)(sV + (r0 + 8) * XSB + n0 * 2) = packbf(acc[mt][nt][2] + bv1[mt], acc[mt][nt][3] + bv1[mt]);
            }
        }
        __syncthreads();

        // keys GEMM
#pragma unroll
        for (int mt = 0; mt < 2; mt++)
#pragma unroll
            for (int nt = 0; nt < 8; nt++)
#pragma unroll
                for (int j = 0; j < 4; j++) acc[mt][nt][j] = 0.f;
        gemm_warpT(aWk, aX, acc, l, rm, cn);

        // per 16-px chunk: exp -> A fragments -> S-MMA (registers only)
#pragma unroll
        for (int kc = 0; kc < 4; kc++) {
#pragma unroll
            for (int mt = 0; mt < 2; mt++) {
                float e00 = fexp(acc[mt][2 * kc][0] + bk0[mt]);
                float e01 = fexp(acc[mt][2 * kc][1] + bk0[mt]);
                float e10 = fexp(acc[mt][2 * kc][2] + bk1[mt]);
                float e11 = fexp(acc[mt][2 * kc][3] + bk1[mt]);
                float e20 = fexp(acc[mt][2 * kc + 1][0] + bk0[mt]);
                float e21 = fexp(acc[mt][2 * kc + 1][1] + bk0[mt]);
                float e30 = fexp(acc[mt][2 * kc + 1][2] + bk1[mt]);
                float e31 = fexp(acc[mt][2 * kc + 1][3] + bk1[mt]);
                zacc[mt][0] += (e00 + e01) + (e20 + e21);
                zacc[mt][1] += (e10 + e11) + (e30 + e31);
                uint32_t ef[4];
                ef[0] = packbf(e00, e01);
                ef[1] = packbf(e10, e11);
                ef[2] = packbf(e20, e21);
                ef[3] = packbf(e30, e31);
                uint32_t bS[4];
                ldsm4(bS, aV + (uint32_t)((h0 + mt) * 16 + (m >> 1) * 8 + lr) * XSB
                             + (m & 1) * 16 + (cn + kc * 16) * 2);
                mma_bf16(accS[mt][0], ef, bS[0], bS[1]);
                mma_bf16(accS[mt][1], ef, bS[2], bS[3]);
            }
        }
        __syncthreads();    // sX / sV reads done before next tile overwrites
    }

    // flush S and Z
#pragma unroll
    for (int mt = 0; mt < 2; mt++) {
        const int h = h0 + mt;
#pragma unroll
        for (int p = 0; p < 2; p++) {
            atomicAdd(&g_S[b][h][g][p * 8 + 2 * tig],         accS[mt][p][0]);
            atomicAdd(&g_S[b][h][g][p * 8 + 2 * tig + 1],     accS[mt][p][1]);
            atomicAdd(&g_S[b][h][g + 8][p * 8 + 2 * tig],     accS[mt][p][2]);
            atomicAdd(&g_S[b][h][g + 8][p * 8 + 2 * tig + 1], accS[mt][p][3]);
        }
    }
#pragma unroll
    for (int mt = 0; mt < 2; mt++)
#pragma unroll
        for (int half = 0; half < 2; half++) {
            float z = zacc[mt][half];
            z += __shfl_xor_sync(0xffffffffu, z, 1);
            z += __shfl_xor_sync(0xffffffffu, z, 2);
            if (tig == 0) atomicAdd(&g_Z[b][rm + mt * 16 + half * 8 + g], z);
        }
}

// ---- G[b][c][hk] = sum_v Wr[c][h*16+v] * S[b][h][k][v] / Z[b][hk] ----
__global__ void gctx_kernel(const float* __restrict__ Wr) {
    int b = blockIdx.x, cc = threadIdx.x;
    for (int hk = 0; hk < C; hk++) {
        int h = hk >> 4, k = hk & 15;
        float a = 0.f;
#pragma unroll
        for (int v = 0; v < 16; v++)
            a += Wr[cc * C + h * 16 + v] * g_S[b][h][k][v];
        g_G[b][cc][hk] = a / g_Z[b][h * 16 + k];
    }
}

// ================= Pass B =================
__global__ void __launch_bounds__(512, 1)
passB_kernel(const float* __restrict__ x, const float* __restrict__ Wq,
             const float* __restrict__ bq, const float* __restrict__ br,
             float* __restrict__ out) {
    extern __shared__ char sm[];
    char* sWq = sm;
    char* sG  = sm + WBUF;
    char* sB0 = sm + 2 * WBUF;
    char* sB1 = sm + 2 * WBUF + XBUF;
    const uint32_t aWq = (uint32_t)__cvta_generic_to_shared(sWq);
    const uint32_t aG  = (uint32_t)__cvta_generic_to_shared(sG);
    const uint32_t aBu[2] = {(uint32_t)__cvta_generic_to_shared(sB0),
                             (uint32_t)__cvta_generic_to_shared(sB1)};
    char* pB[2] = {sB0, sB1};

    const int t = threadIdx.x, l = t & 31, w = t >> 5;
    const int g = l >> 2, tig = l & 3;
    const int rm = (w & 3) * 32, cn = (w >> 2) * 64;
    const int b = blockIdx.y;
    const float* xb = x + (size_t)b * C * NTOT;
    float* ob = out + (size_t)b * C * NTOT;

    load_w(sWq, Wq, t);
    load_w(sG, &g_G[b][0][0], t);
    int tt = blockIdx.x;
    load_x(pB[0], xb + tt * TPX, t);
    __syncthreads();

    float bq0[2], bq1[2], br0[2], br1[2];
#pragma unroll
    for (int mt = 0; mt < 2; mt++) {
        bq0[mt] = bq[rm + mt * 16 + g];     bq1[mt] = bq[rm + mt * 16 + 8 + g];
        br0[mt] = br[rm + mt * 16 + g];     br1[mt] = br[rm + mt * 16 + 8 + g];
    }

    int cur = 0;
    for (; tt < NTILE; tt += BPB) {
        const int nxt = tt + BPB;
        float acc[2][8][4];
#pragma unroll
        for (int mt = 0; mt < 2; mt++)
#pragma unroll
            for (int nt = 0; nt < 8; nt++)
#pragma unroll
                for (int j = 0; j < 4; j++) acc[mt][nt][j] = 0.f;
        gemm_warpT(aWq, aBu[cur], acc, l, rm, cn);

        // exp in place (acc = e)
#pragma unroll
        for (int mt = 0; mt < 2; mt++)
#pragma unroll
            for (int nt = 0; nt < 8; nt++) {
                acc[mt][nt][0] = fexp(acc[mt][nt][0] + bq0[mt]);
                acc[mt][nt][1] = fexp(acc[mt][nt][1] + bq0[mt]);
                acc[mt][nt][2] = fexp(acc[mt][nt][2] + bq1[mt]);
                acc[mt][nt][3] = fexp(acc[mt][nt][3] + bq1[mt]);
            }
        __syncthreads();    // GEMM1 reads of x done; buffer reusable for q

        // normalize (shfl over g-lanes) and store q -> [kq][n] in current buffer
        char* sQ = pB[cur];
#pragma unroll
        for (int mt = 0; mt < 2; mt++) {
            const int r0 = rm + mt * 16 + g;
#pragma unroll
            for (int nt = 0; nt < 8; nt++) {
                float s0 = acc[mt][nt][0] + acc[mt][nt][2];
                float s1 = acc[mt][nt][1] + acc[mt][nt][3];
                s0 += __shfl_xor_sync(0xffffffffu, s0, 4);
                s1 += __shfl_xor_sync(0xffffffffu, s1, 4);
                s0 += __shfl_xor_sync(0xffffffffu, s0, 8);
                s1 += __shfl_xor_sync(0xffffffffu, s1, 8);
                s0 += __shfl_xor_sync(0xffffffffu, s0, 16);
                s1 += __shfl_xor_sync(0xffffffffu, s1, 16);
                float i0 = 1.f / s0, i1 = 1.f / s1;
                const int n0 = cn + nt * 8 + tig * 2;
                *(uint32_t*)(sQ + r0 * XSB + n0 * 2)       = packbf(acc[mt][nt][0] * i0, acc[mt][nt][1] * i1);
                *(uint32_t*)(sQ + (r0 + 8) * XSB + n0 * 2) = packbf(acc[mt][nt][2] * i0, acc[mt][nt][3] * i1);
            }
        }
        if (nxt < NTILE) load_x(pB[cur ^ 1], xb + nxt * TPX, t);
        __syncthreads();

        // out GEMM: D[c][n] = G[c][kq] * q[kq][n]
#pragma unroll
        for (int mt = 0; mt < 2; mt++)
#pragma unroll
            for (int nt = 0; nt < 8; nt++)
#pragma unroll
                for (int j = 0; j < 4; j++) acc[mt][nt][j] = 0.f;
        gemm_warpT(aG, aBu[cur], acc, l, rm, cn);

        // epilogue: out = D + br + x (f32 residual)
#pragma unroll
        for (int mt = 0; mt < 2; mt++) {
            const int r0 = rm + mt * 16 + g;
            const float* x0 = xb + (size_t)r0 * NTOT + tt * TPX;
            const float* x1 = x0 + 8 * NTOT;
            float* o0 = ob + (size_t)r0 * NTOT + tt * TPX;
            float* o1 = o0 + 8 * NTOT;
#pragma unroll
            for (int nt = 0; nt < 8; nt++) {
                const int n0 = cn + nt * 8 + tig * 2;
                float2 xa = *(const float2*)(x0 + n0);
                float2 xc = *(const float2*)(x1 + n0);
                *(float2*)(o0 + n0) = make_float2(acc[mt][nt][0] + br0[mt] + xa.x,
                                                  acc[mt][nt][1] + br0[mt] + xa.y);
                *(float2*)(o1 + n0) = make_float2(acc[mt][nt][2] + br1[mt] + xc.x,
                                                  acc[mt][nt][3] + br1[mt] + xc.y);
            }
        }
        cur ^= 1;
    }
}

extern "C" void kernel_launch(void* const* d_in, const int* in_sizes, int n_in,
                              void* d_out, int out_size) {
    const float* x  = (const float*)d_in[0];
    const float* Wk = (const float*)d_in[1];
    const float* bk = (const float*)d_in[2];
    const float* Wq = (const float*)d_in[3];
    const float* bq = (const float*)d_in[4];
    const float* Wv = (const float*)d_in[5];
    const float* bv = (const float*)d_in[6];
    const float* Wr = (const float*)d_in[7];
    const float* br = (const float*)d_in[8];
    float* out = (float*)d_out;

    const int smem = 2 * WBUF + 2 * XBUF;   // 204,800 B
    cudaFuncSetAttribute(passA_kernel, cudaFuncAttributeMaxDynamicSharedMemorySize, smem);
    cudaFuncSetAttribute(passB_kernel, cudaFuncAttributeMaxDynamicSharedMemorySize, smem);

    zero_kernel<<<128, 256>>>();
    passA_kernel<<<dim3(BPB, BATCH), 512, smem>>>(x, Wk, bk, Wv, bv);
    gctx_kernel<<<BATCH, 128>>>(Wr);
    passB_kernel<<<dim3(BPB, BATCH), 512, smem>>>(x, Wq, bq, br, out);
}